// round 5
// baseline (speedup 1.0000x reference)
#include <cuda_runtime.h>
#include <math.h>

#define N_SITES 100000
#define DIM 128
#define HID 512
#define KVOL 343
#define NPAD 100096   // 782 * 128

// ---- scratch (device globals: zero-initialized at module load; no allocs) ----
__device__ float g_xln[(size_t)NPAD * DIM];   // LN output, tf32-rounded; pad rows stay 0
__device__ float g_h[(size_t)NPAD * HID];     // GELU(pwconv1) output
__device__ float g_sumsq[HID];                // per-channel sum of squares (GRN)
__device__ float g_s[HID];                    // GRN affine scale  (grn_g*nx + 1)
__device__ float g_t[HID];                    // GRN affine shift  (grn_b)

__device__ __forceinline__ float f2tf(float f) {
    unsigned u;
    asm("cvt.rna.tf32.f32 %0, %1;" : "=r"(u) : "f"(f));
    return __uint_as_float(u);
}

__device__ __forceinline__ void mma_tf32(float* c, const unsigned* a, const unsigned* b) {
    asm volatile(
        "mma.sync.aligned.m16n8k8.row.col.f32.tf32.tf32.f32 "
        "{%0,%1,%2,%3}, {%4,%5,%6,%7}, {%8,%9}, {%0,%1,%2,%3};\n"
        : "+f"(c[0]), "+f"(c[1]), "+f"(c[2]), "+f"(c[3])
        : "r"(a[0]), "r"(a[1]), "r"(a[2]), "r"(a[3]), "r"(b[0]), "r"(b[1]));
}

__device__ __forceinline__ float gelu_exact(float v) {
    return 0.5f * v * (1.0f + erff(v * 0.70710678118654752f));
}

// ============================================================================
// K1: sparse depthwise conv (sentinel-skipping) + LayerNorm. 1 site / block.
// ============================================================================
__global__ __launch_bounds__(128) void k_dwln(
    const float* __restrict__ feats, const int* __restrict__ nidx,
    const float* __restrict__ dw_w, const float* __restrict__ dw_b,
    const float* __restrict__ ln_g, const float* __restrict__ ln_b)
{
    const int site = blockIdx.x;
    const int tid  = threadIdx.x;   // 0..127 == channel

    if (site == 0) {  // idempotent zeroing of the GRN accumulator (graph replays!)
        for (int i = tid; i < HID; i += 128) g_sumsq[i] = 0.f;
    }

    __shared__ int   s_idx[KVOL];
    __shared__ int   s_k[KVOL];
    __shared__ int   s_cnt;
    __shared__ float s_red[8];

    // warp 0: deterministic (k-ordered) compaction of valid neighbors
    if (tid < 32) {
        int base = 0;
        const int* row = nidx + (size_t)site * KVOL;
        #pragma unroll
        for (int c = 0; c < 11; ++c) {
            int k = c * 32 + tid;
            int idx = (k < KVOL) ? row[k] : N_SITES;
            bool valid = (idx < N_SITES);
            unsigned m = __ballot_sync(0xffffffffu, valid);
            int pos = base + __popc(m & ((1u << tid) - 1u));
            if (valid) { s_idx[pos] = idx; s_k[pos] = k; }
            base += __popc(m);
        }
        if (tid == 0) s_cnt = base;
    }
    __syncthreads();

    const int cnt = s_cnt;
    float acc = dw_b[tid];
    #pragma unroll 4
    for (int j = 0; j < cnt; ++j) {
        int idx = s_idx[j];
        int k   = s_k[j];
        acc += feats[(size_t)idx * DIM + tid] * dw_w[(size_t)k * DIM + tid];
    }

    // LayerNorm over 128 channels
    float v = acc, v2 = acc * acc;
    #pragma unroll
    for (int o = 16; o > 0; o >>= 1) {
        v  += __shfl_xor_sync(0xffffffffu, v, o);
        v2 += __shfl_xor_sync(0xffffffffu, v2, o);
    }
    int w = tid >> 5, l = tid & 31;
    if (l == 0) { s_red[w] = v; s_red[4 + w] = v2; }
    __syncthreads();
    float sum  = s_red[0] + s_red[1] + s_red[2] + s_red[3];
    float sums = s_red[4] + s_red[5] + s_red[6] + s_red[7];
    float mu  = sum  * (1.f / 128.f);
    float var = sums * (1.f / 128.f) - mu * mu;
    float xn = (acc - mu) * rsqrtf(var + 1e-6f) * ln_g[tid] + ln_b[tid];
    g_xln[(size_t)site * DIM + tid] = f2tf(xn);
}

// ============================================================================
// K2: GEMM1  h = GELU(xln @ w1 + b1)  + per-channel sumsq (GRN stats).
// BM=128, BN=128, BK=32; 8 warps (4m x 2n), warp tile 32x64, tf32 mma.
// ============================================================================
__global__ __launch_bounds__(256) void k_gemm1(
    const float* __restrict__ w1, const float* __restrict__ b1)
{
    __shared__ float sA[128 * 36];
    __shared__ float sB[32 * 136];
    __shared__ float s_csum[128];

    const int tid  = threadIdx.x;
    const int m0   = blockIdx.x * 128;
    const int n0   = blockIdx.y * 128;
    const int warp = tid >> 5, lane = tid & 31;
    const int wm = warp & 3, wn = warp >> 2;
    const int g  = lane >> 2, tg = lane & 3;

    float acc[2][8][4] = {};

    for (int kt = 0; kt < 4; ++kt) {
        const int k0 = kt * 32;
        #pragma unroll
        for (int i = 0; i < 4; ++i) {       // A tile 128x32 (pre-rounded tf32)
            int lin = i * 256 + tid;
            int r = lin >> 3, cv = (lin & 7) * 4;
            float4 v = *(const float4*)&g_xln[(size_t)(m0 + r) * DIM + k0 + cv];
            *(float4*)&sA[r * 36 + cv] = v;
        }
        #pragma unroll
        for (int i = 0; i < 4; ++i) {       // B tile 32x128 from w1 [128,512]
            int lin = i * 256 + tid;
            int r = lin >> 5, cv = (lin & 31) * 4;
            float4 v = *(const float4*)&w1[(size_t)(k0 + r) * HID + n0 + cv];
            v.x = f2tf(v.x); v.y = f2tf(v.y); v.z = f2tf(v.z); v.w = f2tf(v.w);
            *(float4*)&sB[r * 136 + cv] = v;
        }
        __syncthreads();
        #pragma unroll
        for (int k8 = 0; k8 < 4; ++k8) {
            unsigned a[2][4], b[8][2];
            #pragma unroll
            for (int mt = 0; mt < 2; ++mt) {
                int rb = wm * 32 + mt * 16 + g;
                a[mt][0] = __float_as_uint(sA[rb       * 36 + k8 * 8 + tg]);
                a[mt][1] = __float_as_uint(sA[(rb + 8) * 36 + k8 * 8 + tg]);
                a[mt][2] = __float_as_uint(sA[rb       * 36 + k8 * 8 + tg + 4]);
                a[mt][3] = __float_as_uint(sA[(rb + 8) * 36 + k8 * 8 + tg + 4]);
            }
            #pragma unroll
            for (int nt = 0; nt < 8; ++nt) {
                int cb = wn * 64 + nt * 8 + g;
                b[nt][0] = __float_as_uint(sB[(k8 * 8 + tg)     * 136 + cb]);
                b[nt][1] = __float_as_uint(sB[(k8 * 8 + tg + 4) * 136 + cb]);
            }
            #pragma unroll
            for (int mt = 0; mt < 2; ++mt)
                #pragma unroll
                for (int nt = 0; nt < 8; ++nt)
                    mma_tf32(acc[mt][nt], a[mt], b[nt]);
        }
        __syncthreads();
    }

    // epilogue: bias + exact GELU + store h + column sumsq (masked to valid rows)
    if (tid < 128) s_csum[tid] = 0.f;
    __syncthreads();
    #pragma unroll
    for (int nt = 0; nt < 8; ++nt) {
        int colb = wn * 64 + nt * 8 + tg * 2;
        float bias0 = b1[n0 + colb], bias1 = b1[n0 + colb + 1];
        float cs0 = 0.f, cs1 = 0.f;
        #pragma unroll
        for (int mt = 0; mt < 2; ++mt) {
            #pragma unroll
            for (int rh = 0; rh < 2; ++rh) {
                int row = m0 + wm * 32 + mt * 16 + rh * 8 + g;
                float h0 = gelu_exact(acc[mt][nt][rh * 2]     + bias0);
                float h1 = gelu_exact(acc[mt][nt][rh * 2 + 1] + bias1);
                float2 st; st.x = h0; st.y = h1;
                *(float2*)&g_h[(size_t)row * HID + n0 + colb] = st;
                if (row < N_SITES) { cs0 += h0 * h0; cs1 += h1 * h1; }
            }
        }
        atomicAdd(&s_csum[colb], cs0);
        atomicAdd(&s_csum[colb + 1], cs1);
    }
    __syncthreads();
    if (tid < 128) atomicAdd(&g_sumsq[n0 + tid], s_csum[tid]);
}

// ============================================================================
// K3: GRN scale: nx = gx / (mean(gx)+eps);  s = grn_g*nx + 1, t = grn_b.
// ============================================================================
__global__ __launch_bounds__(512) void k_grn(
    const float* __restrict__ grn_g, const float* __restrict__ grn_b)
{
    __shared__ float sred[16];
    __shared__ float smean;
    int c = threadIdx.x;                 // 0..511
    float gx = sqrtf(g_sumsq[c]);
    float v = gx;
    #pragma unroll
    for (int o = 16; o > 0; o >>= 1) v += __shfl_xor_sync(0xffffffffu, v, o);
    if ((c & 31) == 0) sred[c >> 5] = v;
    __syncthreads();
    if (c == 0) {
        float t = 0.f;
        #pragma unroll
        for (int i = 0; i < 16; ++i) t += sred[i];
        smean = t * (1.f / 512.f);
    }
    __syncthreads();
    float nx = gx / (smean + 1e-6f);
    g_s[c] = grn_g[c] * nx + 1.f;
    g_t[c] = grn_b[c];
}

// ============================================================================
// K4: GEMM2  out = feats + (h*s + t) @ w2 + b2.   GRN affine folded into A-load.
// BM=128, BN=128 (full width), BK=32, 16 K-iters.
// ============================================================================
__global__ __launch_bounds__(256) void k_gemm2(
    const float* __restrict__ w2, const float* __restrict__ b2,
    const float* __restrict__ feats, float* __restrict__ out)
{
    __shared__ float sA[128 * 36];
    __shared__ float sB[32 * 136];

    const int tid  = threadIdx.x;
    const int m0   = blockIdx.x * 128;
    const int warp = tid >> 5, lane = tid & 31;
    const int wm = warp & 3, wn = warp >> 2;
    const int g  = lane >> 2, tg = lane & 3;

    float acc[2][8][4] = {};

    for (int kt = 0; kt < 16; ++kt) {
        const int k0 = kt * 32;
        #pragma unroll
        for (int i = 0; i < 4; ++i) {       // A tile: h with GRN affine applied
            int lin = i * 256 + tid;
            int r = lin >> 3, cv = (lin & 7) * 4;
            float4 v  = *(const float4*)&g_h[(size_t)(m0 + r) * HID + k0 + cv];
            float4 s4 = *(const float4*)&g_s[k0 + cv];
            float4 t4 = *(const float4*)&g_t[k0 + cv];
            v.x = f2tf(fmaf(v.x, s4.x, t4.x));
            v.y = f2tf(fmaf(v.y, s4.y, t4.y));
            v.z = f2tf(fmaf(v.z, s4.z, t4.z));
            v.w = f2tf(fmaf(v.w, s4.w, t4.w));
            *(float4*)&sA[r * 36 + cv] = v;
        }
        #pragma unroll
        for (int i = 0; i < 4; ++i) {       // B tile 32x128 from w2 [512,128]
            int lin = i * 256 + tid;
            int r = lin >> 5, cv = (lin & 31) * 4;
            float4 v = *(const float4*)&w2[(size_t)(k0 + r) * DIM + cv];
            v.x = f2tf(v.x); v.y = f2tf(v.y); v.z = f2tf(v.z); v.w = f2tf(v.w);
            *(float4*)&sB[r * 136 + cv] = v;
        }
        __syncthreads();
        #pragma unroll
        for (int k8 = 0; k8 < 4; ++k8) {
            unsigned a[2][4], b[8][2];
            #pragma unroll
            for (int mt = 0; mt < 2; ++mt) {
                int rb = wm * 32 + mt * 16 + g;
                a[mt][0] = __float_as_uint(sA[rb       * 36 + k8 * 8 + tg]);
                a[mt][1] = __float_as_uint(sA[(rb + 8) * 36 + k8 * 8 + tg]);
                a[mt][2] = __float_as_uint(sA[rb       * 36 + k8 * 8 + tg + 4]);
                a[mt][3] = __float_as_uint(sA[(rb + 8) * 36 + k8 * 8 + tg + 4]);
            }
            #pragma unroll
            for (int nt = 0; nt < 8; ++nt) {
                int cb = wn * 64 + nt * 8 + g;
                b[nt][0] = __float_as_uint(sB[(k8 * 8 + tg)     * 136 + cb]);
                b[nt][1] = __float_as_uint(sB[(k8 * 8 + tg + 4) * 136 + cb]);
            }
            #pragma unroll
            for (int mt = 0; mt < 2; ++mt)
                #pragma unroll
                for (int nt = 0; nt < 8; ++nt)
                    mma_tf32(acc[mt][nt], a[mt], b[nt]);
        }
        __syncthreads();
    }

    // epilogue: + b2 + feats residual, masked store
    #pragma unroll
    for (int nt = 0; nt < 8; ++nt) {
        int colb = wn * 64 + nt * 8 + tg * 2;
        float bias0 = b2[colb], bias1 = b2[colb + 1];
        #pragma unroll
        for (int mt = 0; mt < 2; ++mt) {
            #pragma unroll
            for (int rh = 0; rh < 2; ++rh) {
                int row = m0 + wm * 32 + mt * 16 + rh * 8 + g;
                if (row < N_SITES) {
                    float2 f = *(const float2*)&feats[(size_t)row * DIM + colb];
                    float2 st;
                    st.x = acc[mt][nt][rh * 2]     + bias0 + f.x;
                    st.y = acc[mt][nt][rh * 2 + 1] + bias1 + f.y;
                    *(float2*)&out[(size_t)row * DIM + colb] = st;
                }
            }
        }
    }
}

// ============================================================================
extern "C" void kernel_launch(void* const* d_in, const int* in_sizes, int n_in,
                              void* d_out, int out_size)
{
    const float* feats = (const float*)d_in[0];
    const int*   nidx  = (const int*)  d_in[1];
    const float* dw_w  = (const float*)d_in[2];
    const float* dw_b  = (const float*)d_in[3];
    const float* ln_g  = (const float*)d_in[4];
    const float* ln_b  = (const float*)d_in[5];
    const float* w1    = (const float*)d_in[6];
    const float* b1    = (const float*)d_in[7];
    const float* grn_g = (const float*)d_in[8];
    const float* grn_b = (const float*)d_in[9];
    const float* w2    = (const float*)d_in[10];
    const float* b2    = (const float*)d_in[11];
    float* out = (float*)d_out;

    k_dwln<<<N_SITES, 128>>>(feats, nidx, dw_w, dw_b, ln_g, ln_b);
    dim3 g1(NPAD / 128, HID / 128);
    k_gemm1<<<g1, 256>>>(w1, b1);
    k_grn<<<1, 512>>>(grn_g, grn_b);
    k_gemm2<<<NPAD / 128, 256>>>(w2, b2, feats, out);
}

// round 6
// speedup vs baseline: 1.8701x; 1.8701x over previous
#include <cuda_runtime.h>
#include <math.h>

#define N_SITES 100000
#define DIM 128
#define HID 512
#define KVOL 343
#define NPAD 100096   // 782 * 128

// ---- scratch (device globals: zero-initialized; pad rows of g_xln stay 0) ----
__device__ float g_xln[(size_t)NPAD * DIM];   // LN output, tf32-rounded
__device__ float g_h[(size_t)NPAD * HID];     // GELU(pwconv1) output, tf32-rounded
__device__ float g_sumsq[HID];                // per-channel sum of squares (GRN)
__device__ float g_s[HID];                    // GRN affine scale  (grn_g*nx + 1)
__device__ float g_w1t[DIM * HID];            // tf32-rounded w1
__device__ float g_w2t[HID * DIM];            // tf32-rounded  s[k] * w2[k][c]
__device__ float g_bias2[DIM];                // b2 + grn_b @ w2

__device__ __forceinline__ float f2tf(float f) {
    unsigned u;
    asm("cvt.rna.tf32.f32 %0, %1;" : "=r"(u) : "f"(f));
    return __uint_as_float(u);
}

__device__ __forceinline__ void mma_tf32(float* c, const unsigned* a, const unsigned* b) {
    asm volatile(
        "mma.sync.aligned.m16n8k8.row.col.f32.tf32.tf32.f32 "
        "{%0,%1,%2,%3}, {%4,%5,%6,%7}, {%8,%9}, {%0,%1,%2,%3};\n"
        : "+f"(c[0]), "+f"(c[1]), "+f"(c[2]), "+f"(c[3])
        : "r"(a[0]), "r"(a[1]), "r"(a[2]), "r"(a[3]), "r"(b[0]), "r"(b[1]));
}

__device__ __forceinline__ void cpasync16(float* smem, const float* gmem) {
    unsigned s = (unsigned)__cvta_generic_to_shared(smem);
    asm volatile("cp.async.cg.shared.global [%0], [%1], 16;\n" :: "r"(s), "l"(gmem));
}
#define CP_COMMIT() asm volatile("cp.async.commit_group;\n")

__device__ __forceinline__ float gelu_exact(float v) {
    return 0.5f * v * (1.0f + erff(v * 0.70710678118654752f));
}

// ============================================================================
// K1: sparse depthwise conv + LayerNorm.  Warp-per-site, float4 channels.
// ============================================================================
__global__ __launch_bounds__(256) void k_dwln(
    const float* __restrict__ feats, const int* __restrict__ nidx,
    const float* __restrict__ dw_w, const float* __restrict__ dw_b,
    const float* __restrict__ ln_g, const float* __restrict__ ln_b)
{
    __shared__ int s_idx[8][344];
    __shared__ int s_k[8][344];

    const int w    = threadIdx.x >> 5;
    const int lane = threadIdx.x & 31;

    if (blockIdx.x == 0) {  // idempotent zeroing of GRN accumulator (graph replay!)
        for (int i = threadIdx.x; i < HID; i += 256) g_sumsq[i] = 0.f;
    }

    const int site = blockIdx.x * 8 + w;
    if (site >= N_SITES) return;   // whole-warp exit; no block sync used

    // deterministic (k-ordered) per-warp compaction of valid neighbors
    const int* row = nidx + (size_t)site * KVOL;
    int base = 0;
    #pragma unroll
    for (int c = 0; c < 11; ++c) {
        int k = c * 32 + lane;
        int idx = (k < KVOL) ? __ldg(row + k) : N_SITES;
        bool valid = (idx < N_SITES);
        unsigned m = __ballot_sync(0xffffffffu, valid);
        int pos = base + __popc(m & ((1u << lane) - 1u));
        if (valid) { s_idx[w][pos] = idx; s_k[w][pos] = k; }
        base += __popc(m);
    }
    const int cnt = base;
    __syncwarp();

    const int c4 = lane * 4;     // this lane owns channels c4..c4+3
    float4 acc = *(const float4*)&dw_b[c4];
    for (int j = 0; j < cnt; ++j) {
        int idx = s_idx[w][j];
        int k   = s_k[w][j];
        float4 f  = *(const float4*)&feats[(size_t)idx * DIM + c4];
        float4 wt = *(const float4*)&dw_w[(size_t)k   * DIM + c4];
        acc.x = fmaf(f.x, wt.x, acc.x);
        acc.y = fmaf(f.y, wt.y, acc.y);
        acc.z = fmaf(f.z, wt.z, acc.z);
        acc.w = fmaf(f.w, wt.w, acc.w);
    }

    // LayerNorm over 128 channels (warp-wide)
    float s1 = acc.x + acc.y + acc.z + acc.w;
    float s2 = acc.x*acc.x + acc.y*acc.y + acc.z*acc.z + acc.w*acc.w;
    #pragma unroll
    for (int o = 16; o > 0; o >>= 1) {
        s1 += __shfl_xor_sync(0xffffffffu, s1, o);
        s2 += __shfl_xor_sync(0xffffffffu, s2, o);
    }
    float mu  = s1 * (1.f / 128.f);
    float var = s2 * (1.f / 128.f) - mu * mu;
    float inv = rsqrtf(var + 1e-6f);
    float4 g = *(const float4*)&ln_g[c4];
    float4 b = *(const float4*)&ln_b[c4];
    float4 o4;
    o4.x = f2tf((acc.x - mu) * inv * g.x + b.x);
    o4.y = f2tf((acc.y - mu) * inv * g.y + b.y);
    o4.z = f2tf((acc.z - mu) * inv * g.z + b.z);
    o4.w = f2tf((acc.w - mu) * inv * g.w + b.w);
    *(float4*)&g_xln[(size_t)site * DIM + c4] = o4;
}

// ============================================================================
// prep1: tf32-round w1 into g_w1t
// ============================================================================
__global__ __launch_bounds__(256) void k_prep1(const float* __restrict__ w1)
{
    int i = (blockIdx.x * 256 + threadIdx.x) * 4;
    float4 v = *(const float4*)&w1[i];
    v.x = f2tf(v.x); v.y = f2tf(v.y); v.z = f2tf(v.z); v.w = f2tf(v.w);
    *(float4*)&g_w1t[i] = v;
}

// ============================================================================
// K2: GEMM1  h = GELU(xln @ w1 + b1) + per-channel sumsq.
// BM=128, BN=128, BK=32; 8 warps (4m x 2n); 2-stage cp.async pipeline.
// ============================================================================
#define SA_ST 4608   // 128*36
#define SB_ST 4352   // 32*136
#define SMEM_GEMM1 ((2*SA_ST + 2*SB_ST + 128) * 4)
#define SMEM_GEMM2 ((2*SA_ST + 2*SB_ST) * 4)

__global__ __launch_bounds__(256) void k_gemm1(const float* __restrict__ b1)
{
    extern __shared__ float dyn[];
    float* sA = dyn;                       // [2][128*36]
    float* sB = dyn + 2 * SA_ST;           // [2][32*136]
    float* s_csum = dyn + 2 * SA_ST + 2 * SB_ST;

    const int tid  = threadIdx.x;
    const int m0   = blockIdx.x * 128;
    const int n0   = blockIdx.y * 128;
    const int warp = tid >> 5, lane = tid & 31;
    const int wm = warp & 3, wn = warp >> 2;
    const int g  = lane >> 2, tg = lane & 3;

    if (tid < 128) s_csum[tid] = 0.f;

    const int ar = tid >> 3, ac = (tid & 7) * 4;      // A: 4 rows of 32/thread-row
    const int br = tid >> 5, bc = (tid & 31) * 4;     // B

    float acc[2][8][4] = {};

    // prefetch tile 0
    #pragma unroll
    for (int i = 0; i < 4; ++i)
        cpasync16(&sA[(ar + i*32) * 36 + ac], &g_xln[(size_t)(m0 + ar + i*32) * DIM + ac]);
    #pragma unroll
    for (int i = 0; i < 4; ++i)
        cpasync16(&sB[(br + i*8) * 136 + bc], &g_w1t[(size_t)(br + i*8) * HID + n0 + bc]);
    CP_COMMIT();

    for (int kt = 0; kt < 4; ++kt) {
        const int st = kt & 1;
        if (kt < 3) {
            const int k0 = (kt + 1) * 32;
            #pragma unroll
            for (int i = 0; i < 4; ++i)
                cpasync16(&sA[(st^1)*SA_ST + (ar + i*32) * 36 + ac],
                          &g_xln[(size_t)(m0 + ar + i*32) * DIM + k0 + ac]);
            #pragma unroll
            for (int i = 0; i < 4; ++i)
                cpasync16(&sB[(st^1)*SB_ST + (br + i*8) * 136 + bc],
                          &g_w1t[(size_t)(k0 + br + i*8) * HID + n0 + bc]);
            CP_COMMIT();
            asm volatile("cp.async.wait_group 1;\n");
        } else {
            asm volatile("cp.async.wait_group 0;\n");
        }
        __syncthreads();

        const float* cA = sA + st * SA_ST;
        const float* cB = sB + st * SB_ST;
        #pragma unroll
        for (int k8 = 0; k8 < 4; ++k8) {
            unsigned a[2][4], b[8][2];
            #pragma unroll
            for (int mt = 0; mt < 2; ++mt) {
                int rb = wm * 32 + mt * 16 + g;
                a[mt][0] = __float_as_uint(cA[rb       * 36 + k8 * 8 + tg]);
                a[mt][1] = __float_as_uint(cA[(rb + 8) * 36 + k8 * 8 + tg]);
                a[mt][2] = __float_as_uint(cA[rb       * 36 + k8 * 8 + tg + 4]);
                a[mt][3] = __float_as_uint(cA[(rb + 8) * 36 + k8 * 8 + tg + 4]);
            }
            #pragma unroll
            for (int nt = 0; nt < 8; ++nt) {
                int cb = wn * 64 + nt * 8 + g;
                b[nt][0] = __float_as_uint(cB[(k8 * 8 + tg)     * 136 + cb]);
                b[nt][1] = __float_as_uint(cB[(k8 * 8 + tg + 4) * 136 + cb]);
            }
            #pragma unroll
            for (int mt = 0; mt < 2; ++mt)
                #pragma unroll
                for (int nt = 0; nt < 8; ++nt)
                    mma_tf32(acc[mt][nt], a[mt], b[nt]);
        }
        __syncthreads();
    }

    // epilogue: bias + exact GELU + tf32 store + column sumsq (masked)
    #pragma unroll
    for (int nt = 0; nt < 8; ++nt) {
        int colb = wn * 64 + nt * 8 + tg * 2;
        float bias0 = b1[n0 + colb], bias1 = b1[n0 + colb + 1];
        float cs0 = 0.f, cs1 = 0.f;
        #pragma unroll
        for (int mt = 0; mt < 2; ++mt) {
            #pragma unroll
            for (int rh = 0; rh < 2; ++rh) {
                int row = m0 + wm * 32 + mt * 16 + rh * 8 + g;
                float h0 = f2tf(gelu_exact(acc[mt][nt][rh * 2]     + bias0));
                float h1 = f2tf(gelu_exact(acc[mt][nt][rh * 2 + 1] + bias1));
                float2 st2; st2.x = h0; st2.y = h1;
                *(float2*)&g_h[(size_t)row * HID + n0 + colb] = st2;
                if (row < N_SITES) { cs0 += h0 * h0; cs1 += h1 * h1; }
            }
        }
        atomicAdd(&s_csum[colb], cs0);
        atomicAdd(&s_csum[colb + 1], cs1);
    }
    __syncthreads();
    if (tid < 128) atomicAdd(&g_sumsq[n0 + tid], s_csum[tid]);
}

// ============================================================================
// K3: GRN scale: s = grn_g * gx/(mean(gx)+eps) + 1
// ============================================================================
__global__ __launch_bounds__(512) void k_grn(const float* __restrict__ grn_g)
{
    __shared__ float sred[16];
    __shared__ float smean;
    int c = threadIdx.x;
    float gx = sqrtf(g_sumsq[c]);
    float v = gx;
    #pragma unroll
    for (int o = 16; o > 0; o >>= 1) v += __shfl_xor_sync(0xffffffffu, v, o);
    if ((c & 31) == 0) sred[c >> 5] = v;
    __syncthreads();
    if (c == 0) {
        float t = 0.f;
        #pragma unroll
        for (int i = 0; i < 16; ++i) t += sred[i];
        smean = t * (1.f / 512.f);
    }
    __syncthreads();
    g_s[c] = grn_g[c] * (gx / (smean + 1e-6f)) + 1.f;
}

// ============================================================================
// prep2: fold GRN into gemm2 operands.
//  blocks 0..63:  g_w2t[k][c] = f2tf( s[k] * w2[k][c] )
//  block 64:      g_bias2[c]  = b2[c] + sum_k grn_b[k] * w2[k][c]
// ============================================================================
__global__ __launch_bounds__(256) void k_prep2(
    const float* __restrict__ w2, const float* __restrict__ b2,
    const float* __restrict__ grn_b)
{
    if (blockIdx.x < 64) {
        int i = (blockIdx.x * 256 + threadIdx.x) * 4;   // i over 512*128
        int k = i >> 7;                                  // row (HID index)
        float s = g_s[k];
        float4 v = *(const float4*)&w2[i];
        v.x = f2tf(v.x * s); v.y = f2tf(v.y * s);
        v.z = f2tf(v.z * s); v.w = f2tf(v.w * s);
        *(float4*)&g_w2t[i] = v;
    } else if (threadIdx.x < 128) {
        int c = threadIdx.x;
        float acc = b2[c];
        for (int k = 0; k < HID; ++k)
            acc = fmaf(grn_b[k], w2[(size_t)k * DIM + c], acc);
        g_bias2[c] = acc;
    }
}

// ============================================================================
// K4: GEMM2  out = feats + h @ g_w2t + g_bias2.   2-stage cp.async pipeline.
// ============================================================================
__global__ __launch_bounds__(256) void k_gemm2(
    const float* __restrict__ feats, float* __restrict__ out)
{
    extern __shared__ float dyn[];
    float* sA = dyn;
    float* sB = dyn + 2 * SA_ST;

    const int tid  = threadIdx.x;
    const int m0   = blockIdx.x * 128;
    const int warp = tid >> 5, lane = tid & 31;
    const int wm = warp & 3, wn = warp >> 2;
    const int g  = lane >> 2, tg = lane & 3;

    const int ar = tid >> 3, ac = (tid & 7) * 4;
    const int br = tid >> 5, bc = (tid & 31) * 4;

    float acc[2][8][4] = {};

    #pragma unroll
    for (int i = 0; i < 4; ++i)
        cpasync16(&sA[(ar + i*32) * 36 + ac], &g_h[(size_t)(m0 + ar + i*32) * HID + ac]);
    #pragma unroll
    for (int i = 0; i < 4; ++i)
        cpasync16(&sB[(br + i*8) * 136 + bc], &g_w2t[(size_t)(br + i*8) * DIM + bc]);
    CP_COMMIT();

    for (int kt = 0; kt < 16; ++kt) {
        const int st = kt & 1;
        if (kt < 15) {
            const int k0 = (kt + 1) * 32;
            #pragma unroll
            for (int i = 0; i < 4; ++i)
                cpasync16(&sA[(st^1)*SA_ST + (ar + i*32) * 36 + ac],
                          &g_h[(size_t)(m0 + ar + i*32) * HID + k0 + ac]);
            #pragma unroll
            for (int i = 0; i < 4; ++i)
                cpasync16(&sB[(st^1)*SB_ST + (br + i*8) * 136 + bc],
                          &g_w2t[(size_t)(k0 + br + i*8) * DIM + bc]);
            CP_COMMIT();
            asm volatile("cp.async.wait_group 1;\n");
        } else {
            asm volatile("cp.async.wait_group 0;\n");
        }
        __syncthreads();

        const float* cA = sA + st * SA_ST;
        const float* cB = sB + st * SB_ST;
        #pragma unroll
        for (int k8 = 0; k8 < 4; ++k8) {
            unsigned a[2][4], b[8][2];
            #pragma unroll
            for (int mt = 0; mt < 2; ++mt) {
                int rb = wm * 32 + mt * 16 + g;
                a[mt][0] = __float_as_uint(cA[rb       * 36 + k8 * 8 + tg]);
                a[mt][1] = __float_as_uint(cA[(rb + 8) * 36 + k8 * 8 + tg]);
                a[mt][2] = __float_as_uint(cA[rb       * 36 + k8 * 8 + tg + 4]);
                a[mt][3] = __float_as_uint(cA[(rb + 8) * 36 + k8 * 8 + tg + 4]);
            }
            #pragma unroll
            for (int nt = 0; nt < 8; ++nt) {
                int cb = wn * 64 + nt * 8 + g;
                b[nt][0] = __float_as_uint(cB[(k8 * 8 + tg)     * 136 + cb]);
                b[nt][1] = __float_as_uint(cB[(k8 * 8 + tg + 4) * 136 + cb]);
            }
            #pragma unroll
            for (int mt = 0; mt < 2; ++mt)
                #pragma unroll
                for (int nt = 0; nt < 8; ++nt)
                    mma_tf32(acc[mt][nt], a[mt], b[nt]);
        }
        __syncthreads();
    }

    // epilogue: + bias2 + feats residual, masked store
    #pragma unroll
    for (int nt = 0; nt < 8; ++nt) {
        int colb = wn * 64 + nt * 8 + tg * 2;
        float bias0 = g_bias2[colb], bias1 = g_bias2[colb + 1];
        #pragma unroll
        for (int mt = 0; mt < 2; ++mt) {
            #pragma unroll
            for (int rh = 0; rh < 2; ++rh) {
                int row = m0 + wm * 32 + mt * 16 + rh * 8 + g;
                if (row < N_SITES) {
                    float2 f = *(const float2*)&feats[(size_t)row * DIM + colb];
                    float2 st2;
                    st2.x = acc[mt][nt][rh * 2]     + bias0 + f.x;
                    st2.y = acc[mt][nt][rh * 2 + 1] + bias1 + f.y;
                    *(float2*)&out[(size_t)row * DIM + colb] = st2;
                }
            }
        }
    }
}

// ============================================================================
extern "C" void kernel_launch(void* const* d_in, const int* in_sizes, int n_in,
                              void* d_out, int out_size)
{
    const float* feats = (const float*)d_in[0];
    const int*   nidx  = (const int*)  d_in[1];
    const float* dw_w  = (const float*)d_in[2];
    const float* dw_b  = (const float*)d_in[3];
    const float* ln_g  = (const float*)d_in[4];
    const float* ln_b  = (const float*)d_in[5];
    const float* w1    = (const float*)d_in[6];
    const float* b1    = (const float*)d_in[7];
    const float* grn_g = (const float*)d_in[8];
    const float* grn_b = (const float*)d_in[9];
    const float* w2    = (const float*)d_in[10];
    const float* b2    = (const float*)d_in[11];
    float* out = (float*)d_out;

    static bool attr_done = false;
    if (!attr_done) {
        cudaFuncSetAttribute(k_gemm1, cudaFuncAttributeMaxDynamicSharedMemorySize, SMEM_GEMM1);
        cudaFuncSetAttribute(k_gemm2, cudaFuncAttributeMaxDynamicSharedMemorySize, SMEM_GEMM2);
        attr_done = true;
    }

    k_dwln<<<(N_SITES + 7) / 8, 256>>>(feats, nidx, dw_w, dw_b, ln_g, ln_b);
    k_prep1<<<64, 256>>>(w1);
    dim3 g1(NPAD / 128, HID / 128);
    k_gemm1<<<g1, 256, SMEM_GEMM1>>>(b1);
    k_grn<<<1, 512>>>(grn_g);
    k_prep2<<<65, 256>>>(w2, b2, grn_b);
    k_gemm2<<<NPAD / 128, 256, SMEM_GEMM2>>>(feats, out);
}

// round 13
// speedup vs baseline: 2.1091x; 1.1278x over previous
#include <cuda_runtime.h>
#include <cuda_fp16.h>
#include <math.h>
#include <stdint.h>

#define N_SITES 100000
#define DIM 128
#define HID 512
#define KVOL 343
#define NPAD 100096   // 782 * 128

// ---- scratch (device globals: zero-initialized; pad rows stay 0) ----
__device__ __half g_f16[(size_t)N_SITES * DIM];  // fp16 copy of feats (gather source)
__device__ __half g_xln[(size_t)NPAD * DIM];     // LN output fp16; pad rows = 0
__device__ __half g_h[(size_t)NPAD * HID];       // GELU(pwconv1) output fp16
__device__ float  g_sumsq[HID];                  // per-channel sum of squares (GRN)
__device__ float  g_s[HID];                      // GRN affine scale (grn_g*nx + 1)
__device__ __half g_w1T[(size_t)HID * DIM];      // [512][128] = w1^T fp16 (B, K-major)
__device__ __half g_w2T[(size_t)DIM * HID];      // [128][512] = (s*w2)^T fp16
__device__ float  g_bias2[DIM];                  // b2 + grn_b @ w2

// ---------------------------------------------------------------------------
__device__ __forceinline__ float gelu_exact(float v) {
    return 0.5f * v * (1.0f + erff(v * 0.70710678118654752f));
}
__device__ __forceinline__ void cpa16(unsigned smem_dst, const void* gmem) {
    asm volatile("cp.async.cg.shared.global [%0], [%1], 16;\n" :: "r"(smem_dst), "l"(gmem));
}
#define CP_COMMIT() asm volatile("cp.async.commit_group;\n" ::: "memory")

// SW64 swizzle for 64B rows: chunk bits [5:4] ^= row bits [2:1] (bit6=row&1 splits banks)
__device__ __forceinline__ unsigned swz64(unsigned o) { return o ^ ((o >> 3) & 0x30u); }

__device__ __forceinline__ void ldsm4(unsigned* r, unsigned addr) {
    asm volatile("ldmatrix.sync.aligned.m8n8.x4.shared.b16 {%0,%1,%2,%3}, [%4];"
        : "=r"(r[0]), "=r"(r[1]), "=r"(r[2]), "=r"(r[3]) : "r"(addr));
}
__device__ __forceinline__ void mma_f16(float* c, const unsigned* a, const unsigned* b) {
    asm volatile(
        "mma.sync.aligned.m16n8k16.row.col.f32.f16.f16.f32 "
        "{%0,%1,%2,%3}, {%4,%5,%6,%7}, {%8,%9}, {%0,%1,%2,%3};\n"
        : "+f"(c[0]), "+f"(c[1]), "+f"(c[2]), "+f"(c[3])
        : "r"(a[0]), "r"(a[1]), "r"(a[2]), "r"(a[3]), "r"(b[0]), "r"(b[1]));
}

// ============================================================================
// prep0: feats -> fp16 gather copy
// ============================================================================
__global__ __launch_bounds__(256) void k_prep0(const float* __restrict__ feats)
{
    size_t i4 = ((size_t)blockIdx.x * 256 + threadIdx.x) * 4;
    if (i4 >= (size_t)N_SITES * DIM) return;
    float4 v = *(const float4*)&feats[i4];
    __half2 h0 = __floats2half2_rn(v.x, v.y);
    __half2 h1 = __floats2half2_rn(v.z, v.w);
    uint2 st; st.x = *(unsigned*)&h0; st.y = *(unsigned*)&h1;
    *(uint2*)&g_f16[i4] = st;
}

// ============================================================================
// K1: sparse depthwise conv + LayerNorm. Warp-per-site, fp16 gather.
// ============================================================================
__global__ __launch_bounds__(256) void k_dwln(
    const int* __restrict__ nidx,
    const float* __restrict__ dw_w, const float* __restrict__ dw_b,
    const float* __restrict__ ln_g, const float* __restrict__ ln_b)
{
    __shared__ int s_idx[8][344];
    __shared__ int s_k[8][344];

    const int w    = threadIdx.x >> 5;
    const int lane = threadIdx.x & 31;

    if (blockIdx.x == 0) {  // idempotent zeroing of GRN accumulator (graph replay!)
        for (int i = threadIdx.x; i < HID; i += 256) g_sumsq[i] = 0.f;
    }

    const int site = blockIdx.x * 8 + w;
    if (site >= N_SITES) return;

    const int* row = nidx + (size_t)site * KVOL;
    int base = 0;
    #pragma unroll
    for (int c = 0; c < 11; ++c) {
        int k = c * 32 + lane;
        int idx = (k < KVOL) ? __ldg(row + k) : N_SITES;
        bool valid = (idx < N_SITES);
        unsigned m = __ballot_sync(0xffffffffu, valid);
        int pos = base + __popc(m & ((1u << lane) - 1u));
        if (valid) { s_idx[w][pos] = idx; s_k[w][pos] = k; }
        base += __popc(m);
    }
    const int cnt = base;
    __syncwarp();

    const int c4 = lane * 4;
    float4 acc = *(const float4*)&dw_b[c4];
    for (int j = 0; j < cnt; ++j) {
        int idx = s_idx[w][j];
        int k   = s_k[w][j];
        uint2 u = *(const uint2*)&g_f16[(size_t)idx * DIM + c4];
        float2 f01 = __half22float2(*reinterpret_cast<__half2*>(&u.x));
        float2 f23 = __half22float2(*reinterpret_cast<__half2*>(&u.y));
        float4 wt = *(const float4*)&dw_w[(size_t)k * DIM + c4];
        acc.x = fmaf(f01.x, wt.x, acc.x);
        acc.y = fmaf(f01.y, wt.y, acc.y);
        acc.z = fmaf(f23.x, wt.z, acc.z);
        acc.w = fmaf(f23.y, wt.w, acc.w);
    }

    float s1 = acc.x + acc.y + acc.z + acc.w;
    float s2 = acc.x*acc.x + acc.y*acc.y + acc.z*acc.z + acc.w*acc.w;
    #pragma unroll
    for (int o = 16; o > 0; o >>= 1) {
        s1 += __shfl_xor_sync(0xffffffffu, s1, o);
        s2 += __shfl_xor_sync(0xffffffffu, s2, o);
    }
    float mu  = s1 * (1.f / 128.f);
    float var = s2 * (1.f / 128.f) - mu * mu;
    float inv = rsqrtf(var + 1e-6f);
    float4 g = *(const float4*)&ln_g[c4];
    float4 b = *(const float4*)&ln_b[c4];
    __half2 o01 = __floats2half2_rn((acc.x - mu) * inv * g.x + b.x,
                                    (acc.y - mu) * inv * g.y + b.y);
    __half2 o23 = __floats2half2_rn((acc.z - mu) * inv * g.z + b.z,
                                    (acc.w - mu) * inv * g.w + b.w);
    uint2 st; st.x = *(unsigned*)&o01; st.y = *(unsigned*)&o23;
    *(uint2*)&g_xln[(size_t)site * DIM + c4] = st;
}

// ============================================================================
// prep1: g_w1T[n][k] = fp16(w1[k][n])
// ============================================================================
__global__ __launch_bounds__(256) void k_prep1(const float* __restrict__ w1)
{
    int idx = blockIdx.x * 256 + threadIdx.x;    // over 512*128
    int n = idx >> 7, k = idx & 127;
    g_w1T[idx] = __float2half_rn(w1[(size_t)k * HID + n]);
}

// ============================================================================
// K2: GEMM1  h = GELU(xln @ w1 + b1) + per-channel sumsq.
// BM=128, BN=128, K=128 (4 K-tiles, all resident). fp16 mma m16n8k16 + ldmatrix.
// smem: A tiles [0,32K), B tiles [32K,64K), csum @64K, bias @64.5K
// ============================================================================
#define G1_SMEM (66560 + 1024)
#define G2_SMEM (66048 + 1024)

__global__ __launch_bounds__(256) void k_gemm1(const float* __restrict__ b1)
{
    extern __shared__ char smem[];
    unsigned sraw = (unsigned)__cvta_generic_to_shared(smem);
    unsigned sal  = (sraw + 1023u) & ~1023u;
    char* smal    = smem + (sal - sraw);

    const int tid = threadIdx.x, lane = tid & 31, warp = tid >> 5;
    const int wm = warp & 3, wn = warp >> 2;
    const int g = lane >> 2, tg = lane & 3;
    const int m0 = blockIdx.x * 128, n0 = blockIdx.y * 128;

    float* s_csum = (float*)(smal + 65536);
    float* s_bias = (float*)(smal + 66048);
    if (tid < 128) { s_csum[tid] = 0.f; s_bias[tid] = b1[n0 + tid]; }

    // issue all 4 K-tile loads (A 8KB + B 8KB per tile), one commit group each
    #pragma unroll
    for (int kt = 0; kt < 4; ++kt) {
        #pragma unroll
        for (int j = 0; j < 2; ++j) {
            int chunk = tid * 2 + j;              // 0..511
            int r = chunk >> 2, c = chunk & 3;
            cpa16(sal + kt * 8192 + swz64(r * 64 + c * 16),
                  g_xln + (size_t)(m0 + r) * DIM + kt * 32 + c * 8);
            cpa16(sal + 32768 + kt * 8192 + swz64(r * 64 + c * 16),
                  g_w1T + (size_t)(n0 + r) * DIM + kt * 32 + c * 8);
        }
        CP_COMMIT();
    }

    // per-lane ldmatrix offsets
    unsigned aoff[2][2], boff[4][2];
    {
        int i = lane >> 3;
        #pragma unroll
        for (int mt = 0; mt < 2; ++mt)
            #pragma unroll
            for (int ks = 0; ks < 2; ++ks)
                aoff[mt][ks] = swz64((wm*32 + mt*16 + (i&1)*8 + (lane&7)) * 64
                                     + ks*32 + (i>>1)*16);
        #pragma unroll
        for (int p = 0; p < 4; ++p)
            #pragma unroll
            for (int ks = 0; ks < 2; ++ks)
                boff[p][ks] = swz64((wn*64 + p*16 + (i>>1)*8 + (lane&7)) * 64
                                     + ks*32 + (i&1)*16);
    }

    float acc[2][8][4] = {};
    #pragma unroll
    for (int kt = 0; kt < 4; ++kt) {
        if      (kt == 0) asm volatile("cp.async.wait_group 3;\n" ::: "memory");
        else if (kt == 1) asm volatile("cp.async.wait_group 2;\n" ::: "memory");
        else if (kt == 2) asm volatile("cp.async.wait_group 1;\n" ::: "memory");
        else              asm volatile("cp.async.wait_group 0;\n" ::: "memory");
        __syncthreads();
        unsigned aB = sal + kt * 8192, bB = sal + 32768 + kt * 8192;
        #pragma unroll
        for (int ks = 0; ks < 2; ++ks) {
            unsigned af[2][4], bf[4][4];
            ldsm4(af[0], aB + aoff[0][ks]);
            ldsm4(af[1], aB + aoff[1][ks]);
            #pragma unroll
            for (int p = 0; p < 4; ++p) ldsm4(bf[p], bB + boff[p][ks]);
            #pragma unroll
            for (int mt = 0; mt < 2; ++mt)
                #pragma unroll
                for (int nt = 0; nt < 8; ++nt)
                    mma_f16(acc[mt][nt], af[mt], &bf[nt >> 1][(nt & 1) * 2]);
        }
    }

    // epilogue: bias + exact GELU + fp16 store + column sumsq (masked)
    #pragma unroll
    for (int nt = 0; nt < 8; ++nt) {
        int colb = wn * 64 + nt * 8 + tg * 2;
        float bb0 = s_bias[colb], bb1 = s_bias[colb + 1];
        float cs0 = 0.f, cs1 = 0.f;
        #pragma unroll
        for (int mt = 0; mt < 2; ++mt) {
            #pragma unroll
            for (int rh = 0; rh < 2; ++rh) {
                int row = m0 + wm * 32 + mt * 16 + rh * 8 + g;
                float h0 = gelu_exact(acc[mt][nt][rh * 2]     + bb0);
                float h1 = gelu_exact(acc[mt][nt][rh * 2 + 1] + bb1);
                *(__half2*)&g_h[(size_t)row * HID + n0 + colb] = __floats2half2_rn(h0, h1);
                if (row < N_SITES) { cs0 += h0 * h0; cs1 += h1 * h1; }
            }
        }
        atomicAdd(&s_csum[colb], cs0);
        atomicAdd(&s_csum[colb + 1], cs1);
    }
    __syncthreads();
    if (tid < 128) atomicAdd(&g_sumsq[n0 + tid], s_csum[tid]);
}

// ============================================================================
// K3: GRN scale: s = grn_g * gx/(mean(gx)+eps) + 1
// ============================================================================
__global__ __launch_bounds__(512) void k_grn(const float* __restrict__ grn_g)
{
    __shared__ float sred[16];
    __shared__ float smean;
    int c = threadIdx.x;
    float gx = sqrtf(g_sumsq[c]);
    float v = gx;
    #pragma unroll
    for (int o = 16; o > 0; o >>= 1) v += __shfl_xor_sync(0xffffffffu, v, o);
    if ((c & 31) == 0) sred[c >> 5] = v;
    __syncthreads();
    if (c == 0) {
        float t = 0.f;
        #pragma unroll
        for (int i = 0; i < 16; ++i) t += sred[i];
        smean = t * (1.f / 512.f);
    }
    __syncthreads();
    g_s[c] = grn_g[c] * (gx / (smean + 1e-6f)) + 1.f;
}

// ============================================================================
// prep2: g_w2T[n][k] = fp16(s[k]*w2[k][n]);  block 256: bias2 = b2 + grn_b @ w2
// ============================================================================
__global__ __launch_bounds__(256) void k_prep2(
    const float* __restrict__ w2, const float* __restrict__ b2,
    const float* __restrict__ grn_b)
{
    if (blockIdx.x < 256) {
        int idx = blockIdx.x * 256 + threadIdx.x;    // over 128*512
        int n = idx >> 9, k = idx & 511;
        g_w2T[idx] = __float2half_rn(g_s[k] * w2[(size_t)k * DIM + n]);
    } else if (threadIdx.x < 128) {
        int c = threadIdx.x;
        float acc = b2[c];
        for (int k = 0; k < HID; ++k)
            acc = fmaf(grn_b[k], w2[(size_t)k * DIM + c], acc);
        g_bias2[c] = acc;
    }
}

// ============================================================================
// K4: GEMM2  out = feats + h @ w2T + bias2.
// BM=128, BN=128, 16 K-tiles; 4-stage cp.async ring. fp16 mma + ldmatrix.
// ============================================================================
__global__ __launch_bounds__(256) void k_gemm2(
    const float* __restrict__ feats, float* __restrict__ out)
{
    extern __shared__ char smem[];
    unsigned sraw = (unsigned)__cvta_generic_to_shared(smem);
    unsigned sal  = (sraw + 1023u) & ~1023u;
    char* smal    = smem + (sal - sraw);

    const int tid = threadIdx.x, lane = tid & 31, warp = tid >> 5;
    const int wm = warp & 3, wn = warp >> 2;
    const int g = lane >> 2, tg = lane & 3;
    const int m0 = blockIdx.x * 128;

    float* s_b2 = (float*)(smal + 65536);
    if (tid < 128) s_b2[tid] = g_bias2[tid];

    auto load_tile = [&](int kt) {
        int st = kt & 3;
        #pragma unroll
        for (int j = 0; j < 2; ++j) {
            int chunk = tid * 2 + j;
            int r = chunk >> 2, c = chunk & 3;
            cpa16(sal + st * 8192 + swz64(r * 64 + c * 16),
                  g_h + (size_t)(m0 + r) * HID + kt * 32 + c * 8);
            cpa16(sal + 32768 + st * 8192 + swz64(r * 64 + c * 16),
                  g_w2T + (size_t)r * HID + kt * 32 + c * 8);
        }
        CP_COMMIT();
    };
    load_tile(0); load_tile(1); load_tile(2);

    unsigned aoff[2][2], boff[4][2];
    {
        int i = lane >> 3;
        #pragma unroll
        for (int mt = 0; mt < 2; ++mt)
            #pragma unroll
            for (int ks = 0; ks < 2; ++ks)
                aoff[mt][ks] = swz64((wm*32 + mt*16 + (i&1)*8 + (lane&7)) * 64
                                     + ks*32 + (i>>1)*16);
        #pragma unroll
        for (int p = 0; p < 4; ++p)
            #pragma unroll
            for (int ks = 0; ks < 2; ++ks)
                boff[p][ks] = swz64((wn*64 + p*16 + (i>>1)*8 + (lane&7)) * 64
                                     + ks*32 + (i&1)*16);
    }

    float acc[2][8][4] = {};
    for (int kt = 0; kt < 16; ++kt) {
        if      (kt < 14)  asm volatile("cp.async.wait_group 2;\n" ::: "memory");
        else if (kt == 14) asm volatile("cp.async.wait_group 1;\n" ::: "memory");
        else               asm volatile("cp.async.wait_group 0;\n" ::: "memory");
        __syncthreads();
        if (kt < 13) load_tile(kt + 3);

        int st = kt & 3;
        unsigned aB = sal + st * 8192, bB = sal + 32768 + st * 8192;
        #pragma unroll
        for (int ks = 0; ks < 2; ++ks) {
            unsigned af[2][4], bf[4][4];
            ldsm4(af[0], aB + aoff[0][ks]);
            ldsm4(af[1], aB + aoff[1][ks]);
            #pragma unroll
            for (int p = 0; p < 4; ++p) ldsm4(bf[p], bB + boff[p][ks]);
            #pragma unroll
            for (int mt = 0; mt < 2; ++mt)
                #pragma unroll
                for (int nt = 0; nt < 8; ++nt)
                    mma_f16(acc[mt][nt], af[mt], &bf[nt >> 1][(nt & 1) * 2]);
        }
    }

    // epilogue: + bias2 + feats residual, masked store
    #pragma unroll
    for (int nt = 0; nt < 8; ++nt) {
        int colb = wn * 64 + nt * 8 + tg * 2;
        float bb0 = s_b2[colb], bb1 = s_b2[colb + 1];
        #pragma unroll
        for (int mt = 0; mt < 2; ++mt) {
            #pragma unroll
            for (int rh = 0; rh < 2; ++rh) {
                int row = m0 + wm * 32 + mt * 16 + rh * 8 + g;
                if (row < N_SITES) {
                    float2 f = *(const float2*)&feats[(size_t)row * DIM + colb];
                    float2 st2;
                    st2.x = acc[mt][nt][rh * 2]     + bb0 + f.x;
                    st2.y = acc[mt][nt][rh * 2 + 1] + bb1 + f.y;
                    *(float2*)&out[(size_t)row * DIM + colb] = st2;
                }
            }
        }
    }
}

// ============================================================================
extern "C" void kernel_launch(void* const* d_in, const int* in_sizes, int n_in,
                              void* d_out, int out_size)
{
    const float* feats = (const float*)d_in[0];
    const int*   nidx  = (const int*)  d_in[1];
    const float* dw_w  = (const float*)d_in[2];
    const float* dw_b  = (const float*)d_in[3];
    const float* ln_g  = (const float*)d_in[4];
    const float* ln_b  = (const float*)d_in[5];
    const float* w1    = (const float*)d_in[6];
    const float* b1    = (const float*)d_in[7];
    const float* grn_g = (const float*)d_in[8];
    const float* grn_b = (const float*)d_in[9];
    const float* w2    = (const float*)d_in[10];
    const float* b2    = (const float*)d_in[11];
    float* out = (float*)d_out;

    static bool attr_done = false;
    if (!attr_done) {
        cudaFuncSetAttribute(k_gemm1, cudaFuncAttributeMaxDynamicSharedMemorySize, G1_SMEM);
        cudaFuncSetAttribute(k_gemm2, cudaFuncAttributeMaxDynamicSharedMemorySize, G2_SMEM);
        attr_done = true;
    }

    k_prep0<<<(N_SITES * DIM) / 1024, 256>>>(feats);
    k_dwln<<<N_SITES / 8, 256>>>(nidx, dw_w, dw_b, ln_g, ln_b);
    k_prep1<<<(HID * DIM) / 256, 256>>>(w1);
    dim3 g1(NPAD / 128, HID / 128);
    k_gemm1<<<g1, 256, G1_SMEM>>>(b1);
    k_grn<<<1, 512>>>(grn_g);
    k_prep2<<<257, 256>>>(w2, b2, grn_b);
    k_gemm2<<<NPAD / 128, 256, G2_SMEM>>>(feats, out);
}

// round 14
// speedup vs baseline: 2.7535x; 1.3055x over previous
#include <cuda_runtime.h>
#include <cuda_fp16.h>
#include <math.h>
#include <stdint.h>

#define N_SITES 100000
#define DIM 128
#define HID 512
#define KVOL 343
#define NPAD 100096   // 782 * 128

// ---- scratch (device globals: zero-initialized; pad rows stay 0) ----
__device__ __half g_f16[(size_t)N_SITES * DIM];  // fp16 copy of feats (gather source)
__device__ __half g_xln[(size_t)NPAD * DIM];     // LN output fp16; pad rows = 0
__device__ __half g_h[(size_t)NPAD * HID];       // GELU(pwconv1) output fp16
__device__ float  g_sumsq[HID];                  // per-channel sum of squares (GRN)
__device__ float  g_s[HID];                      // GRN affine scale (grn_g*nx + 1)
__device__ __half g_w1T[(size_t)HID * DIM];      // [512][128] = w1^T fp16 (B, K-major)
__device__ __half g_w2T[(size_t)DIM * HID];      // [128][512] = (s*w2)^T fp16
__device__ float  g_bias2[DIM];                  // b2 + grn_b @ w2

// ---------------------------------------------------------------------------
__device__ __forceinline__ float gelu_exact(float v) {
    return 0.5f * v * (1.0f + erff(v * 0.70710678118654752f));
}
__device__ __forceinline__ void cpa16(unsigned smem_dst, const void* gmem) {
    asm volatile("cp.async.cg.shared.global [%0], [%1], 16;\n" :: "r"(smem_dst), "l"(gmem));
}
#define CP_COMMIT() asm volatile("cp.async.commit_group;\n" ::: "memory")

// SW64 swizzle for 64B rows: chunk bits [5:4] ^= row bits [2:1]
__device__ __forceinline__ unsigned swz64(unsigned o) { return o ^ ((o >> 3) & 0x30u); }

__device__ __forceinline__ void ldsm4(unsigned* r, unsigned addr) {
    asm volatile("ldmatrix.sync.aligned.m8n8.x4.shared.b16 {%0,%1,%2,%3}, [%4];"
        : "=r"(r[0]), "=r"(r[1]), "=r"(r[2]), "=r"(r[3]) : "r"(addr));
}
__device__ __forceinline__ void mma_f16(float* c, const unsigned* a, const unsigned* b) {
    asm volatile(
        "mma.sync.aligned.m16n8k16.row.col.f32.f16.f16.f32 "
        "{%0,%1,%2,%3}, {%4,%5,%6,%7}, {%8,%9}, {%0,%1,%2,%3};\n"
        : "+f"(c[0]), "+f"(c[1]), "+f"(c[2]), "+f"(c[3])
        : "r"(a[0]), "r"(a[1]), "r"(a[2]), "r"(a[3]), "r"(b[0]), "r"(b[1]));
}

// ============================================================================
// prep0: feats -> fp16 gather copy
// ============================================================================
__global__ __launch_bounds__(256) void k_prep0(const float* __restrict__ feats)
{
    size_t i4 = ((size_t)blockIdx.x * 256 + threadIdx.x) * 4;
    if (i4 >= (size_t)N_SITES * DIM) return;
    float4 v = *(const float4*)&feats[i4];
    __half2 h0 = __floats2half2_rn(v.x, v.y);
    __half2 h1 = __floats2half2_rn(v.z, v.w);
    uint2 st; st.x = *(unsigned*)&h0; st.y = *(unsigned*)&h1;
    *(uint2*)&g_f16[i4] = st;
}

// ============================================================================
// K1: sparse depthwise conv + LayerNorm. Warp-per-site, fp16 gather.
// ============================================================================
__global__ __launch_bounds__(256) void k_dwln(
    const int* __restrict__ nidx,
    const float* __restrict__ dw_w, const float* __restrict__ dw_b,
    const float* __restrict__ ln_g, const float* __restrict__ ln_b)
{
    __shared__ int s_idx[8][344];
    __shared__ int s_k[8][344];

    const int w    = threadIdx.x >> 5;
    const int lane = threadIdx.x & 31;

    if (blockIdx.x == 0) {  // idempotent zeroing of GRN accumulator (graph replay!)
        for (int i = threadIdx.x; i < HID; i += 256) g_sumsq[i] = 0.f;
    }

    const int site = blockIdx.x * 8 + w;
    if (site >= N_SITES) return;

    const int* row = nidx + (size_t)site * KVOL;
    int base = 0;
    #pragma unroll
    for (int c = 0; c < 11; ++c) {
        int k = c * 32 + lane;
        int idx = (k < KVOL) ? __ldg(row + k) : N_SITES;
        bool valid = (idx < N_SITES);
        unsigned m = __ballot_sync(0xffffffffu, valid);
        int pos = base + __popc(m & ((1u << lane) - 1u));
        if (valid) { s_idx[w][pos] = idx; s_k[w][pos] = k; }
        base += __popc(m);
    }
    const int cnt = base;
    __syncwarp();

    const int c4 = lane * 4;
    float4 acc = *(const float4*)&dw_b[c4];
    for (int j = 0; j < cnt; ++j) {
        int idx = s_idx[w][j];
        int k   = s_k[w][j];
        uint2 u = *(const uint2*)&g_f16[(size_t)idx * DIM + c4];
        float2 f01 = __half22float2(*reinterpret_cast<__half2*>(&u.x));
        float2 f23 = __half22float2(*reinterpret_cast<__half2*>(&u.y));
        float4 wt = *(const float4*)&dw_w[(size_t)k * DIM + c4];
        acc.x = fmaf(f01.x, wt.x, acc.x);
        acc.y = fmaf(f01.y, wt.y, acc.y);
        acc.z = fmaf(f23.x, wt.z, acc.z);
        acc.w = fmaf(f23.y, wt.w, acc.w);
    }

    float s1 = acc.x + acc.y + acc.z + acc.w;
    float s2 = acc.x*acc.x + acc.y*acc.y + acc.z*acc.z + acc.w*acc.w;
    #pragma unroll
    for (int o = 16; o > 0; o >>= 1) {
        s1 += __shfl_xor_sync(0xffffffffu, s1, o);
        s2 += __shfl_xor_sync(0xffffffffu, s2, o);
    }
    float mu  = s1 * (1.f / 128.f);
    float var = s2 * (1.f / 128.f) - mu * mu;
    float inv = rsqrtf(var + 1e-6f);
    float4 g = *(const float4*)&ln_g[c4];
    float4 b = *(const float4*)&ln_b[c4];
    __half2 o01 = __floats2half2_rn((acc.x - mu) * inv * g.x + b.x,
                                    (acc.y - mu) * inv * g.y + b.y);
    __half2 o23 = __floats2half2_rn((acc.z - mu) * inv * g.z + b.z,
                                    (acc.w - mu) * inv * g.w + b.w);
    uint2 st; st.x = *(unsigned*)&o01; st.y = *(unsigned*)&o23;
    *(uint2*)&g_xln[(size_t)site * DIM + c4] = st;
}

// ============================================================================
// prep1: g_w1T[n][k] = fp16(w1[k][n])
// ============================================================================
__global__ __launch_bounds__(256) void k_prep1(const float* __restrict__ w1)
{
    int idx = blockIdx.x * 256 + threadIdx.x;    // over 512*128
    int n = idx >> 7, k = idx & 127;
    g_w1T[idx] = __float2half_rn(w1[(size_t)k * HID + n]);
}

// ============================================================================
// K2: GEMM1  h = GELU(xln @ w1 + b1) + per-channel sumsq.
// BM=128, BN=128, K=128 (4 K-tiles, all resident). fp16 mma + ldmatrix.
// Epilogue: smem staging (padded stride) -> coalesced 16B stores; sumsq
// computed during the copy (8 channels/thread) + shfl-reduced atomics.
// ============================================================================
#define G1_SMEM (66560 + 1024)
#define G2_SMEM (68096 + 1024)

__global__ __launch_bounds__(256) void k_gemm1(const float* __restrict__ b1)
{
    extern __shared__ char smem[];
    unsigned sraw = (unsigned)__cvta_generic_to_shared(smem);
    unsigned sal  = (sraw + 1023u) & ~1023u;
    char* smal    = smem + (sal - sraw);

    const int tid = threadIdx.x, lane = tid & 31, warp = tid >> 5;
    const int wm = warp & 3, wn = warp >> 2;
    const int g = lane >> 2, tg = lane & 3;
    const int m0 = blockIdx.x * 128, n0 = blockIdx.y * 128;

    float* s_csum = (float*)(smal + 65536);
    float* s_bias = (float*)(smal + 66048);
    if (tid < 128) { s_csum[tid] = 0.f; s_bias[tid] = b1[n0 + tid]; }

    // issue all 4 K-tile loads (A 8KB + B 8KB per tile), one commit group each
    #pragma unroll
    for (int kt = 0; kt < 4; ++kt) {
        #pragma unroll
        for (int j = 0; j < 2; ++j) {
            int chunk = tid * 2 + j;              // 0..511
            int r = chunk >> 2, c = chunk & 3;
            cpa16(sal + kt * 8192 + swz64(r * 64 + c * 16),
                  g_xln + (size_t)(m0 + r) * DIM + kt * 32 + c * 8);
            cpa16(sal + 32768 + kt * 8192 + swz64(r * 64 + c * 16),
                  g_w1T + (size_t)(n0 + r) * DIM + kt * 32 + c * 8);
        }
        CP_COMMIT();
    }

    // per-lane ldmatrix offsets
    unsigned aoff[2][2], boff[4][2];
    {
        int i = lane >> 3;
        #pragma unroll
        for (int mt = 0; mt < 2; ++mt)
            #pragma unroll
            for (int ks = 0; ks < 2; ++ks)
                aoff[mt][ks] = swz64((wm*32 + mt*16 + (i&1)*8 + (lane&7)) * 64
                                     + ks*32 + (i>>1)*16);
        #pragma unroll
        for (int p = 0; p < 4; ++p)
            #pragma unroll
            for (int ks = 0; ks < 2; ++ks)
                boff[p][ks] = swz64((wn*64 + p*16 + (i>>1)*8 + (lane&7)) * 64
                                     + ks*32 + (i&1)*16);
    }

    float acc[2][8][4] = {};
    #pragma unroll
    for (int kt = 0; kt < 4; ++kt) {
        if      (kt == 0) asm volatile("cp.async.wait_group 3;\n" ::: "memory");
        else if (kt == 1) asm volatile("cp.async.wait_group 2;\n" ::: "memory");
        else if (kt == 2) asm volatile("cp.async.wait_group 1;\n" ::: "memory");
        else              asm volatile("cp.async.wait_group 0;\n" ::: "memory");
        __syncthreads();
        unsigned aB = sal + kt * 8192, bB = sal + 32768 + kt * 8192;
        #pragma unroll
        for (int ks = 0; ks < 2; ++ks) {
            unsigned af[2][4], bf[4][4];
            ldsm4(af[0], aB + aoff[0][ks]);
            ldsm4(af[1], aB + aoff[1][ks]);
            #pragma unroll
            for (int p = 0; p < 4; ++p) ldsm4(bf[p], bB + boff[p][ks]);
            #pragma unroll
            for (int mt = 0; mt < 2; ++mt)
                #pragma unroll
                for (int nt = 0; nt < 8; ++nt)
                    mma_f16(acc[mt][nt], af[mt], &bf[nt >> 1][(nt & 1) * 2]);
        }
    }
    __syncthreads();                       // tile smem now reusable for staging

    // --- stage bias+GELU results into smem (stride 136 halves = 272B, 16B-aligned rows)
    __half* hst = (__half*)smal;
    #pragma unroll
    for (int nt = 0; nt < 8; ++nt) {
        int colb = wn * 64 + nt * 8 + tg * 2;
        float bb0 = s_bias[colb], bb1 = s_bias[colb + 1];
        #pragma unroll
        for (int mt = 0; mt < 2; ++mt) {
            #pragma unroll
            for (int rh = 0; rh < 2; ++rh) {
                int row = wm * 32 + mt * 16 + rh * 8 + g;
                float h0 = gelu_exact(acc[mt][nt][rh * 2]     + bb0);
                float h1 = gelu_exact(acc[mt][nt][rh * 2 + 1] + bb1);
                *(__half2*)&hst[row * 136 + colb] = __floats2half2_rn(h0, h1);
            }
        }
    }
    __syncthreads();

    // --- coalesced 16B stores + per-channel sumsq (8 fixed channels/thread)
    const int cc = tid & 15;               // 16B chunk within row (8 channels)
    const int r0 = tid >> 4;
    float sq[8] = {};
    #pragma unroll
    for (int k = 0; k < 8; ++k) {
        int r = r0 + k * 16;
        uint4 v = *(uint4*)&hst[r * 136 + cc * 8];
        *(uint4*)&g_h[(size_t)(m0 + r) * HID + n0 + cc * 8] = v;
        if (m0 + r < N_SITES) {
            __half2* hp = (__half2*)&v;
            #pragma unroll
            for (int q = 0; q < 4; ++q) {
                float2 f = __half22float2(hp[q]);
                sq[q * 2]     += f.x * f.x;
                sq[q * 2 + 1] += f.y * f.y;
            }
        }
    }
    #pragma unroll
    for (int q = 0; q < 8; ++q)
        sq[q] += __shfl_xor_sync(0xffffffffu, sq[q], 16);
    if ((lane & 16) == 0) {
        #pragma unroll
        for (int q = 0; q < 8; ++q)
            atomicAdd(&s_csum[cc * 8 + q], sq[q]);
    }
    __syncthreads();
    if (tid < 128) atomicAdd(&g_sumsq[n0 + tid], s_csum[tid]);
}

// ============================================================================
// K3: GRN scale: s = grn_g * gx/(mean(gx)+eps) + 1
// ============================================================================
__global__ __launch_bounds__(512) void k_grn(const float* __restrict__ grn_g)
{
    __shared__ float sred[16];
    __shared__ float smean;
    int c = threadIdx.x;
    float gx = sqrtf(g_sumsq[c]);
    float v = gx;
    #pragma unroll
    for (int o = 16; o > 0; o >>= 1) v += __shfl_xor_sync(0xffffffffu, v, o);
    if ((c & 31) == 0) sred[c >> 5] = v;
    __syncthreads();
    if (c == 0) {
        float t = 0.f;
        #pragma unroll
        for (int i = 0; i < 16; ++i) t += sred[i];
        smean = t * (1.f / 512.f);
    }
    __syncthreads();
    g_s[c] = grn_g[c] * (gx / (smean + 1e-6f)) + 1.f;
}

// ============================================================================
// prep2: g_w2T[n][k] = fp16(s[k]*w2[k][n]);  block 256: bias2 = b2 + grn_b @ w2
// ============================================================================
__global__ __launch_bounds__(256) void k_prep2(
    const float* __restrict__ w2, const float* __restrict__ b2,
    const float* __restrict__ grn_b)
{
    if (blockIdx.x < 256) {
        int idx = blockIdx.x * 256 + threadIdx.x;    // over 128*512
        int n = idx >> 9, k = idx & 511;
        g_w2T[idx] = __float2half_rn(g_s[k] * w2[(size_t)k * DIM + n]);
    } else if (threadIdx.x < 128) {
        int c = threadIdx.x;
        float acc = b2[c];
        for (int k = 0; k < HID; ++k)
            acc = fmaf(grn_b[k], w2[(size_t)k * DIM + c], acc);
        g_bias2[c] = acc;
    }
}

// ============================================================================
// K4: GEMM2  out = feats + h @ w2T + bias2.
// BM=128, BN=128, 16 K-tiles; 4-stage cp.async ring. fp16 mma + ldmatrix.
// Epilogue: smem staging (stride 132 floats) -> coalesced residual+store.
// ============================================================================
__global__ __launch_bounds__(256) void k_gemm2(
    const float* __restrict__ feats, float* __restrict__ out)
{
    extern __shared__ char smem[];
    unsigned sraw = (unsigned)__cvta_generic_to_shared(smem);
    unsigned sal  = (sraw + 1023u) & ~1023u;
    char* smal    = smem + (sal - sraw);

    const int tid = threadIdx.x, lane = tid & 31, warp = tid >> 5;
    const int wm = warp & 3, wn = warp >> 2;
    const int g = lane >> 2, tg = lane & 3;
    const int m0 = blockIdx.x * 128;

    float* s_b2 = (float*)(smal + 67584);
    if (tid < 128) s_b2[tid] = g_bias2[tid];

    auto load_tile = [&](int kt) {
        int st = kt & 3;
        #pragma unroll
        for (int j = 0; j < 2; ++j) {
            int chunk = tid * 2 + j;
            int r = chunk >> 2, c = chunk & 3;
            cpa16(sal + st * 8192 + swz64(r * 64 + c * 16),
                  g_h + (size_t)(m0 + r) * HID + kt * 32 + c * 8);
            cpa16(sal + 32768 + st * 8192 + swz64(r * 64 + c * 16),
                  g_w2T + (size_t)r * HID + kt * 32 + c * 8);
        }
        CP_COMMIT();
    };
    load_tile(0); load_tile(1); load_tile(2);

    unsigned aoff[2][2], boff[4][2];
    {
        int i = lane >> 3;
        #pragma unroll
        for (int mt = 0; mt < 2; ++mt)
            #pragma unroll
            for (int ks = 0; ks < 2; ++ks)
                aoff[mt][ks] = swz64((wm*32 + mt*16 + (i&1)*8 + (lane&7)) * 64
                                     + ks*32 + (i>>1)*16);
        #pragma unroll
        for (int p = 0; p < 4; ++p)
            #pragma unroll
            for (int ks = 0; ks < 2; ++ks)
                boff[p][ks] = swz64((wn*64 + p*16 + (i>>1)*8 + (lane&7)) * 64
                                     + ks*32 + (i&1)*16);
    }

    float acc[2][8][4] = {};
    for (int kt = 0; kt < 16; ++kt) {
        if      (kt < 14)  asm volatile("cp.async.wait_group 2;\n" ::: "memory");
        else if (kt == 14) asm volatile("cp.async.wait_group 1;\n" ::: "memory");
        else               asm volatile("cp.async.wait_group 0;\n" ::: "memory");
        __syncthreads();
        if (kt < 13) load_tile(kt + 3);

        int st = kt & 3;
        unsigned aB = sal + st * 8192, bB = sal + 32768 + st * 8192;
        #pragma unroll
        for (int ks = 0; ks < 2; ++ks) {
            unsigned af[2][4], bf[4][4];
            ldsm4(af[0], aB + aoff[0][ks]);
            ldsm4(af[1], aB + aoff[1][ks]);
            #pragma unroll
            for (int p = 0; p < 4; ++p) ldsm4(bf[p], bB + boff[p][ks]);
            #pragma unroll
            for (int mt = 0; mt < 2; ++mt)
                #pragma unroll
                for (int nt = 0; nt < 8; ++nt)
                    mma_f16(acc[mt][nt], af[mt], &bf[nt >> 1][(nt & 1) * 2]);
        }
    }
    __syncthreads();                       // pipeline smem now reusable

    // --- stage acc+bias into smem (stride 132 floats = 528B, 16B-aligned rows)
    float* fst = (float*)smal;
    #pragma unroll
    for (int nt = 0; nt < 8; ++nt) {
        int colb = wn * 64 + nt * 8 + tg * 2;
        float bb0 = s_b2[colb], bb1 = s_b2[colb + 1];
        #pragma unroll
        for (int mt = 0; mt < 2; ++mt) {
            #pragma unroll
            for (int rh = 0; rh < 2; ++rh) {
                int row = wm * 32 + mt * 16 + rh * 8 + g;
                float2 v;
                v.x = acc[mt][nt][rh * 2]     + bb0;
                v.y = acc[mt][nt][rh * 2 + 1] + bb1;
                *(float2*)&fst[row * 132 + colb] = v;
            }
        }
    }
    __syncthreads();

    // --- coalesced residual + store
    const int cc = tid & 31, r0 = tid >> 5;
    #pragma unroll
    for (int k = 0; k < 16; ++k) {
        int r = r0 + k * 8;
        int grow = m0 + r;
        if (grow < N_SITES) {
            float4 v = *(float4*)&fst[r * 132 + cc * 4];
            float4 f = *(const float4*)&feats[(size_t)grow * DIM + cc * 4];
            v.x += f.x; v.y += f.y; v.z += f.z; v.w += f.w;
            *(float4*)&out[(size_t)grow * DIM + cc * 4] = v;
        }
    }
}

// ============================================================================
extern "C" void kernel_launch(void* const* d_in, const int* in_sizes, int n_in,
                              void* d_out, int out_size)
{
    const float* feats = (const float*)d_in[0];
    const int*   nidx  = (const int*)  d_in[1];
    const float* dw_w  = (const float*)d_in[2];
    const float* dw_b  = (const float*)d_in[3];
    const float* ln_g  = (const float*)d_in[4];
    const float* ln_b  = (const float*)d_in[5];
    const float* w1    = (const float*)d_in[6];
    const float* b1    = (const float*)d_in[7];
    const float* grn_g = (const float*)d_in[8];
    const float* grn_b = (const float*)d_in[9];
    const float* w2    = (const float*)d_in[10];
    const float* b2    = (const float*)d_in[11];
    float* out = (float*)d_out;

    static bool attr_done = false;
    if (!attr_done) {
        cudaFuncSetAttribute(k_gemm1, cudaFuncAttributeMaxDynamicSharedMemorySize, G1_SMEM);
        cudaFuncSetAttribute(k_gemm2, cudaFuncAttributeMaxDynamicSharedMemorySize, G2_SMEM);
        attr_done = true;
    }

    k_prep0<<<(N_SITES * DIM) / 1024, 256>>>(feats);
    k_dwln<<<N_SITES / 8, 256>>>(nidx, dw_w, dw_b, ln_g, ln_b);
    k_prep1<<<(HID * DIM) / 256, 256>>>(w1);
    dim3 g1(NPAD / 128, HID / 128);
    k_gemm1<<<g1, 256, G1_SMEM>>>(b1);
    k_grn<<<1, 512>>>(grn_g);
    k_prep2<<<257, 256>>>(w2, b2, grn_b);
    k_gemm2<<<NPAD / 128, 256, G2_SMEM>>>(feats, out);
}